// round 4
// baseline (speedup 1.0000x reference)
#include <cuda_runtime.h>
#include <math.h>
#include <stdint.h>

#define BSZ 256
#define TT_ 512
#define ADIM 8
#define ZDIM 4
#define KMIX 3
#define HL 50
#define HID 128
#define NROWS (BSZ*TT_)

// ---------------- scratch (static __device__; cudaMalloc forbidden) ----------------
__device__ float g_buf1[NROWS*HID];
__device__ float g_buf2[NROWS*HID];
__device__ float g_a[NROWS*ADIM];
__device__ float g_alpha[NROWS*KMIX];
__device__ float g_mup[NROWS*ZDIM];
__device__ float g_muf[NROWS*ZDIM];
__device__ float g_J[NROWS*ZDIM*ZDIM];
__device__ float g_mus[NROWS*ZDIM];
__device__ float g_ahat[NROWS*ADIM];

// ---------------- fast activations (EX2/RCP MUFU based; rel err ~1e-7) -------------
__device__ __forceinline__ float fsig(float x){
    return __fdividef(1.f, 1.f + __expf(-x));
}
__device__ __forceinline__ float ftanh(float x){
    float xc = fminf(fmaxf(x, -15.f), 15.f);
    float t = __expf(2.f*xc);
    return __fdividef(t-1.f, t+1.f);
}

template<int ACT>
__device__ __forceinline__ float actf(float v){
    if (ACT == 1) return ftanh(v);
    if (ACT == 2) return fsig(v);
    return v;
}

// ---------------- generic fused SGEMM: C[M,128] = act(A[M,K] @ W[128,K]^T + bias) ----
// Software-pipelined: next K-tile is loaded to registers during current tile compute.
template<int ACT, bool CONCAT>
__global__ __launch_bounds__(256,2)
void sgemm128(const float* __restrict__ A0, const float* __restrict__ A1,
              const float* __restrict__ W, const float* __restrict__ bias,
              float* __restrict__ C, int K)
{
    __shared__ __align__(16) float As[16][132];
    __shared__ __align__(16) float Bsm[16][132];
    const int tid = threadIdx.x;
    const int row0 = blockIdx.x * 128;
    const int tx = tid & 15, ty = tid >> 4;
    float acc[8][8];
#pragma unroll
    for (int i=0;i<8;i++)
#pragma unroll
        for (int j=0;j<8;j++) acc[i][j]=0.f;

    float4 ra[2], rb[2];
    const int q0 = tid, q1 = tid+256;
    const int r0_=q0>>2, kc0=(q0&3)<<2;
    const int r1_=q1>>2, kc1=(q1&3)<<2;

    // prologue load of tile k0=0
    {
        const float* srcA0; const float* srcA1;
        if (CONCAT){
            srcA0 = (kc0<128)? (A0+(size_t)(row0+r0_)*128+kc0) : (A1+(size_t)(row0+r0_)*128+(kc0-128));
            srcA1 = (kc1<128)? (A0+(size_t)(row0+r1_)*128+kc1) : (A1+(size_t)(row0+r1_)*128+(kc1-128));
        } else {
            srcA0 = A0+(size_t)(row0+r0_)*K+kc0;
            srcA1 = A0+(size_t)(row0+r1_)*K+kc1;
        }
        ra[0]=*(const float4*)srcA0;
        ra[1]=*(const float4*)srcA1;
        rb[0]=*(const float4*)(W+(size_t)r0_*K+kc0);
        rb[1]=*(const float4*)(W+(size_t)r1_*K+kc1);
    }

    for (int k0=0;k0<K;k0+=16){
        __syncthreads();  // previous compute done before smem overwrite (no-op first iter)
        As[kc0+0][r0_]=ra[0].x; As[kc0+1][r0_]=ra[0].y; As[kc0+2][r0_]=ra[0].z; As[kc0+3][r0_]=ra[0].w;
        As[kc1+0][r1_]=ra[1].x; As[kc1+1][r1_]=ra[1].y; As[kc1+2][r1_]=ra[1].z; As[kc1+3][r1_]=ra[1].w;
        Bsm[kc0+0][r0_]=rb[0].x; Bsm[kc0+1][r0_]=rb[0].y; Bsm[kc0+2][r0_]=rb[0].z; Bsm[kc0+3][r0_]=rb[0].w;
        Bsm[kc1+0][r1_]=rb[1].x; Bsm[kc1+1][r1_]=rb[1].y; Bsm[kc1+2][r1_]=rb[1].z; Bsm[kc1+3][r1_]=rb[1].w;
        __syncthreads();
        int kn = k0+16;
        if (kn<K){
            const float* srcA0; const float* srcA1;
            if (CONCAT){
                int g0=kn+kc0, g1=kn+kc1;
                srcA0 = (g0<128)? (A0+(size_t)(row0+r0_)*128+g0) : (A1+(size_t)(row0+r0_)*128+(g0-128));
                srcA1 = (g1<128)? (A0+(size_t)(row0+r1_)*128+g1) : (A1+(size_t)(row0+r1_)*128+(g1-128));
            } else {
                srcA0 = A0+(size_t)(row0+r0_)*K+kn+kc0;
                srcA1 = A0+(size_t)(row0+r1_)*K+kn+kc1;
            }
            ra[0]=*(const float4*)srcA0;
            ra[1]=*(const float4*)srcA1;
            rb[0]=*(const float4*)(W+(size_t)r0_*K+kn+kc0);
            rb[1]=*(const float4*)(W+(size_t)r1_*K+kn+kc1);
        }
#pragma unroll
        for (int k=0;k<16;k++){
            float4 a0=*(const float4*)&As[k][ty*8];
            float4 a1=*(const float4*)&As[k][ty*8+4];
            float4 b0=*(const float4*)&Bsm[k][tx*8];
            float4 b1=*(const float4*)&Bsm[k][tx*8+4];
            float av[8]={a0.x,a0.y,a0.z,a0.w,a1.x,a1.y,a1.z,a1.w};
            float bv[8]={b0.x,b0.y,b0.z,b0.w,b1.x,b1.y,b1.z,b1.w};
#pragma unroll
            for (int i=0;i<8;i++)
#pragma unroll
                for (int j=0;j<8;j++)
                    acc[i][j] += av[i]*bv[j];
        }
    }
    float bn[8];
#pragma unroll
    for (int j=0;j<8;j++) bn[j]=bias[tx*8+j];
#pragma unroll
    for (int i=0;i<8;i++){
        size_t gr = (size_t)row0 + ty*8 + i;
        float4 o0, o1;
        o0.x=actf<ACT>(acc[i][0]+bn[0]); o0.y=actf<ACT>(acc[i][1]+bn[1]);
        o0.z=actf<ACT>(acc[i][2]+bn[2]); o0.w=actf<ACT>(acc[i][3]+bn[3]);
        o1.x=actf<ACT>(acc[i][4]+bn[4]); o1.y=actf<ACT>(acc[i][5]+bn[5]);
        o1.z=actf<ACT>(acc[i][6]+bn[6]); o1.w=actf<ACT>(acc[i][7]+bn[7]);
        *(float4*)&C[gr*128 + tx*8]     = o0;
        *(float4*)&C[gr*128 + tx*8 + 4] = o1;
    }
}

// ---------------- encoder layer 3: a = Y2 @ Wm^T + bm + eps  (N=8, K=128) ----------
__global__ __launch_bounds__(256)
void enc3_kernel(const float* __restrict__ Y2, const float* __restrict__ Wm,
                 const float* __restrict__ bm, const float* __restrict__ eps,
                 float* __restrict__ aout)
{
    __shared__ __align__(16) float sW[8][128];
    for (int i=threadIdx.x;i<1024;i+=256) sW[i>>7][i&127]=Wm[i];
    __syncthreads();
    int r = blockIdx.x*32 + (threadIdx.x>>3);
    int n = threadIdx.x&7;
    const float4* y = (const float4*)(Y2 + (size_t)r*128);
    const float4* w = (const float4*)&sW[n][0];
    float s=0.f;
#pragma unroll
    for (int k=0;k<32;k++){
        float4 yv=y[k], wv=w[k];
        s += yv.x*wv.x+yv.y*wv.y+yv.z*wv.z+yv.w*wv.w;
    }
    aout[(size_t)r*8+n] = s + bm[n] + eps[(size_t)r*8+n];
}

// ---------------- LSTM + alpha: ONE barrier per step, gate quads within a warp -----
// Thread tid<200: unit j=tid>>2, gate type k=tid&3 (i,f,g,o), weight row = k*50+j.
// Activation applied per-thread; f,g,o shuffled to the k=0 lane which owns c_j, h_j.
// h double-buffered so warp 7 (alpha for t-1, x prefetch) reads h_{t-1} race-free.
__global__ __launch_bounds__(256)
void lstm_kernel(const float* __restrict__ a, const float* __restrict__ a_init,
                 const float* __restrict__ Wih, const float* __restrict__ Whh,
                 const float* __restrict__ bih, const float* __restrict__ bhh,
                 const float* __restrict__ aW, const float* __restrict__ ab,
                 float* __restrict__ alpha)
{
    __shared__ __align__(16) float4 shv[2][13];   // h double-buffered, padded to 52
    __shared__ __align__(16) float4 sxv[2][2];    // x_t double-buffered (8)
    __shared__ __align__(16) float4 saWv[3][13];
    __shared__ float sab_s[3];
    int tid=threadIdx.x; int b=blockIdx.x;

    float wih[8], whh[52], bsum=0.f, c=0.f;
    if (tid<200){
        int k=tid&3, j=tid>>2;
        int row=k*50+j;
#pragma unroll
        for (int jj=0;jj<8;jj++) wih[jj]=Wih[row*8+jj];
#pragma unroll
        for (int jj=0;jj<50;jj++) whh[jj]=Whh[row*50+jj];
        whh[50]=0.f; whh[51]=0.f;
        bsum=bih[row]+bhh[row];
    }
    for (int i=tid;i<3*52;i+=256){
        int r2=i/52, c2=i%52;
        ((float*)saWv)[i] = (c2<50)? aW[r2*50+c2] : 0.f;
    }
    if (tid<3) sab_s[tid]=ab[tid];
    for (int i=tid;i<104;i+=256) ((float*)shv)[i]=0.f;   // both h buffers (pads stay 0)
    if (tid<8) ((float*)sxv)[tid]=a_init[tid];           // sxv[0] = x_0 = a_init
    __syncthreads();

    for (int t=0;t<TT_;t++){
        int pb=t&1;
        if (tid<224){
            // gates (tid<200); lanes 200-223 ride along for the shuffles
            float pre=0.f;
            if (tid<200){
                const float4* xv=sxv[pb];
                float4 x0=xv[0], x1=xv[1];
                float a0=bsum + wih[0]*x0.x + wih[4]*x1.x;
                float a1=wih[1]*x0.y + wih[5]*x1.y;
                float a2=wih[2]*x0.z + wih[6]*x1.z;
                float a3=wih[3]*x0.w + wih[7]*x1.w;
                const float4* hv4=shv[pb];
#pragma unroll
                for (int q=0;q<13;q++){
                    float4 hv=hv4[q];
                    a0+=whh[4*q+0]*hv.x; a1+=whh[4*q+1]*hv.y;
                    a2+=whh[4*q+2]*hv.z; a3+=whh[4*q+3]*hv.w;
                }
                pre=(a0+a1)+(a2+a3);
            }
            float val = ((tid&3)==2)? ftanh(pre) : fsig(pre);
            unsigned lbase=(tid&31)&~3u;
            float vf=__shfl_sync(0xffffffffu,val,lbase+1);
            float vg=__shfl_sync(0xffffffffu,val,lbase+2);
            float vo=__shfl_sync(0xffffffffu,val,lbase+3);
            if (tid<200 && (tid&3)==0){
                c = vf*c + val*vg;                         // sig(f)*c + sig(i)*tanh(g)
                ((float*)shv[pb^1])[tid>>2] = vo*ftanh(c); // h_t
            }
        } else {
            int lt=tid-224;
            if (lt<3){
                if (t>0){
                    // alpha_{t-1} from h_{t-1} = shv[pb]; each thread computes all 3 logits
                    float lg[3];
#pragma unroll
                    for (int kk=0;kk<3;kk++){
                        float a0=0,a1=0,a2=0,a3=0;
#pragma unroll
                        for (int q=0;q<13;q++){
                            float4 wv=saWv[kk][q], hv=shv[pb][q];
                            a0+=wv.x*hv.x; a1+=wv.y*hv.y; a2+=wv.z*hv.z; a3+=wv.w*hv.w;
                        }
                        lg[kk]=(a0+a1)+(a2+a3)+sab_s[kk];
                    }
                    float mx=fmaxf(lg[0],fmaxf(lg[1],lg[2]));
                    float e0=__expf(lg[0]-mx),e1=__expf(lg[1]-mx),e2=__expf(lg[2]-mx);
                    float inv=__fdividef(1.f,e0+e1+e2);
                    float mine=(lt==0)?e0:((lt==1)?e1:e2);
                    alpha[((size_t)b*TT_+t-1)*3+lt]=mine*inv;
                }
            } else if (lt>=8 && lt<16){
                if (t<TT_-1)
                    ((float*)sxv[pb^1])[lt-8]=a[((size_t)b*TT_+t)*8+(lt-8)];
            }
        }
        __syncthreads();
    }
    // final alpha (t=T-1): h_{T-1} sits in shv[0] (last write at t=511, pb=1 -> pb^1=0)
    if (tid>=224 && tid<227){
        int lt=tid-224;
        float lg[3];
#pragma unroll
        for (int kk=0;kk<3;kk++){
            float a0=0,a1=0,a2=0,a3=0;
#pragma unroll
            for (int q=0;q<13;q++){
                float4 wv=saWv[kk][q], hv=shv[0][q];
                a0+=wv.x*hv.x; a1+=wv.y*hv.y; a2+=wv.z*hv.z; a3+=wv.w*hv.w;
            }
            lg[kk]=(a0+a1)+(a2+a3)+sab_s[kk];
        }
        float mx=fmaxf(lg[0],fmaxf(lg[1],lg[2]));
        float e0=__expf(lg[0]-mx),e1=__expf(lg[1]-mx),e2=__expf(lg[2]-mx);
        float inv=__fdividef(1.f,e0+e1+e2);
        float mine=(lt==0)?e0:((lt==1)?e1:e2);
        alpha[((size_t)b*TT_+TT_-1)*3+lt]=mine*inv;
    }
}

// ---------------- 4x4 determinant + adjugate helpers --------------------------------
__device__ __forceinline__ float det4s(const float* m){
    float m00=m[0],m01=m[1],m02=m[2],m03=m[3];
    float m10=m[4],m11=m[5],m12=m[6],m13=m[7];
    float m20=m[8],m21=m[9],m22=m[10],m23=m[11];
    float m30=m[12],m31=m[13],m32=m[14],m33=m[15];
    return m00*(m11*(m22*m33-m23*m32)-m12*(m21*m33-m23*m31)+m13*(m21*m32-m22*m31))
         - m01*(m10*(m22*m33-m23*m32)-m12*(m20*m33-m23*m30)+m13*(m20*m32-m22*m30))
         + m02*(m10*(m21*m33-m23*m31)-m11*(m20*m33-m23*m30)+m13*(m20*m31-m21*m30))
         - m03*(m10*(m21*m32-m22*m31)-m11*(m20*m32-m22*m30)+m12*(m20*m31-m21*m30));
}

__device__ __forceinline__ float adj_entry(const float* m, int l){
    int r=l>>2, c=l&3;
    int rr[3], cc[3];
    int p=0;
#pragma unroll
    for (int k=0;k<4;k++) if (k!=c) rr[p++]=k;
    p=0;
#pragma unroll
    for (int k=0;k<4;k++) if (k!=r) cc[p++]=k;
    float a00=m[rr[0]*4+cc[0]], a01=m[rr[0]*4+cc[1]], a02=m[rr[0]*4+cc[2]];
    float a10=m[rr[1]*4+cc[0]], a11=m[rr[1]*4+cc[1]], a12=m[rr[1]*4+cc[2]];
    float a20=m[rr[2]*4+cc[0]], a21=m[rr[2]*4+cc[1]], a22=m[rr[2]*4+cc[2]];
    float d = a00*(a11*a22-a12*a21) - a01*(a10*a22-a12*a20) + a02*(a10*a21-a11*a20);
    return ((r+c)&1)? -d : d;
}

// ---------------- Kalman forward + smoother gains (information form, 9 phases) -----
#define KO_AM   0
#define KO_BM   16
#define KO_CM   52
#define KO_SIG  84
#define KO_SIGP 100
#define KO_PADJ 116
#define KO_CTC  132
#define KO_N    148
#define KO_NADJ 164
#define KO_T2   180
#define KO_JT   196
#define KO_KG   212
#define KO_MU   244
#define KO_MUP  248
#define KO_RES  252
#define KO_AT   260
#define KO_UT   268
#define KO_AL   277
#define KO_SC   280
#define KWSZ    288

__global__ __launch_bounds__(64)
void kf_forward(const float* __restrict__ alpha, const float* __restrict__ a,
                const float* __restrict__ a_init, const float* __restrict__ u_ext,
                const float* __restrict__ Ag, const float* __restrict__ Bg,
                const float* __restrict__ Cg,
                float* __restrict__ mu_p_g, float* __restrict__ mu_f_g,
                float* __restrict__ Jg)
{
    __shared__ float sA[48], sB[108], sC[96];
    __shared__ float wsm[2][KWSZ];
    const float qn=0.08f, ir=1.f/0.03f;
    int w = threadIdx.x>>5, ln = threadIdx.x&31;
    int b = blockIdx.x*2 + w;
    for (int i=threadIdx.x;i<48;i+=64) sA[i]=Ag[i];
    for (int i=threadIdx.x;i<108;i+=64) sB[i]=Bg[i];
    for (int i=threadIdx.x;i<96;i+=64) sC[i]=Cg[i];
    __syncthreads();
    float* s = wsm[w];

    float r_al=0.f, r_a=0.f, r_u=0.f, r_ap=0.f;
    if (ln<3)            r_al = alpha[(size_t)b*TT_*3 + ln];
    if (ln>=4 && ln<12){ r_a  = a[(size_t)b*TT_*8 + (ln-4)]; r_ap = a_init[ln-4]; }
    if (ln==12)          r_u  = u_ext[(size_t)b*TT_];

    for (int t=0;t<TT_;t++){
        size_t bt = (size_t)b*TT_ + t;
        if (ln<3) s[KO_AL+ln]=r_al;
        if (ln>=4 && ln<12){ s[KO_AT+ln-4]=r_a; s[KO_UT+ln-4]=r_ap; r_ap=r_a; }
        if (ln==12) s[KO_UT+8]=r_u;
        __syncwarp();
        if (t+1<TT_){
            if (ln<3)            r_al = alpha[(bt+1)*3+ln];
            if (ln>=4 && ln<12)  r_a  = a[(bt+1)*8 + (ln-4)];
            if (ln==12)          r_u  = u_ext[bt+1];
        }
        float al0=s[KO_AL], al1=s[KO_AL+1], al2=s[KO_AL+2];
        for (int f=ln; f<84; f+=32){
            if (f<16)      s[KO_AM+f] = al0*sA[f] + al1*sA[16+f] + al2*sA[32+f];
            else if (f<52){int j2=f-16; s[KO_BM+j2]=al0*sB[j2]+al1*sB[36+j2]+al2*sB[72+j2];}
            else          {int j2=f-52; s[KO_CM+j2]=al0*sC[j2]+al1*sC[32+j2]+al2*sC[64+j2];}
        }
        __syncwarp();
        if (t==0){
            if (ln<4) s[KO_MUP+ln]=0.f;
            if (ln>=16){int l=ln-16; s[KO_SIGP+l]=((l>>2)==(l&3))?20.f:0.f;}
        } else {
            if (ln<4){
                float v=0.f;
#pragma unroll
                for (int j=0;j<4;j++) v += s[KO_AM+ln*4+j]*s[KO_MU+j];
#pragma unroll
                for (int j=0;j<9;j++) v += s[KO_BM+ln*9+j]*s[KO_UT+j];
                s[KO_MUP+ln]=v;
            }
            if (ln>=16){
                int l=ln-16, i=l>>2, j=l&3;
                float v=(i==j)?qn:0.f;
#pragma unroll
                for (int k=0;k<4;k++){
                    float inner=0.f;
#pragma unroll
                    for (int q=0;q<4;q++) inner += s[KO_SIG+k*4+q]*s[KO_AM+j*4+q];
                    v += s[KO_AM+i*4+k]*inner;
                }
                s[KO_SIGP+l]=v;
            }
        }
        if (ln>=4 && ln<14){
            const int pi_[10]={0,0,0,0,1,1,1,2,2,3};
            const int pj_[10]={0,1,2,3,1,2,3,2,3,3};
            int l=ln-4, i=pi_[l], j=pj_[l];
            float v=0.f;
#pragma unroll
            for (int cc=0;cc<8;cc++) v += s[KO_CM+cc*4+i]*s[KO_CM+cc*4+j];
            v*=ir;
            s[KO_CTC+i*4+j]=v; s[KO_CTC+j*4+i]=v;
        }
        __syncwarp();
        if (ln<16) s[KO_PADJ+ln]=adj_entry(s+KO_SIGP, ln);
        else if (t>0){
            int l=ln-16, i=l>>2, j=l&3; float v=0.f;
#pragma unroll
            for (int k=0;k<4;k++) v += s[KO_SIG+i*4+k]*s[KO_AM+j*4+k];
            s[KO_T2+l]=v;
        }
        __syncwarp();
        if (ln==0){
            float dp = s[KO_SIGP+0]*s[KO_PADJ+0] + s[KO_SIGP+1]*s[KO_PADJ+4]
                     + s[KO_SIGP+2]*s[KO_PADJ+8] + s[KO_SIGP+3]*s[KO_PADJ+12];
            s[KO_SC+0]=dp;
            s[KO_SC+1]=__fdividef(1.f,dp);
        }
        if (ln>=8 && ln<16){
            int cc=ln-8; float v=s[KO_AT+cc];
#pragma unroll
            for (int k=0;k<4;k++) v -= s[KO_CM+cc*4+k]*s[KO_MUP+k];
            s[KO_RES+cc]=v;
        }
        if (t>0 && ln>=16){
            int l=ln-16, i=l>>2, j=l&3; float v=0.f;
#pragma unroll
            for (int k=0;k<4;k++) v += s[KO_T2+i*4+k]*s[KO_PADJ+k*4+j];
            s[KO_JT+l]=v;
        }
        __syncwarp();
        if (ln<16) s[KO_N+ln] = s[KO_PADJ+ln] + s[KO_SC+0]*s[KO_CTC+ln];
        else if (t>0){
            int l=ln-16;
            Jg[(bt-1)*16 + l] = s[KO_JT+l]*s[KO_SC+1];
        }
        __syncwarp();
        if (ln<16) s[KO_NADJ+ln]=adj_entry(s+KO_N, ln);
        if (ln==16){
            float dn = det4s(s+KO_N);
            float sc = __fdividef(s[KO_SC+0], dn);
            s[KO_SC+2]=sc;
            s[KO_SC+3]=sc*ir;
        }
        __syncwarp();
        {
            int i=ln>>3, cc=ln&7; float v=0.f;
#pragma unroll
            for (int k=0;k<4;k++) v += s[KO_NADJ+i*4+k]*s[KO_CM+cc*4+k];
            s[KO_KG+i*8+cc]=v;
        }
        __syncwarp();
        if (ln>=16){
            int l=ln-16;
            s[KO_SIG+l]=s[KO_NADJ+l]*s[KO_SC+2];
        }
        if (ln<4){
            float acc=0.f;
#pragma unroll
            for (int cc=0;cc<8;cc++) acc += s[KO_KG+ln*8+cc]*s[KO_RES+cc];
            float v = s[KO_MUP+ln] + acc*s[KO_SC+3];
            s[KO_MU+ln]=v;
            mu_f_g[bt*4+ln]=v;
        }
        if (ln>=4 && ln<8) mu_p_g[bt*4+ln-4]=s[KO_MUP+ln-4];
        __syncwarp();
    }
}

// ---------------- backward mu_smooth recursion (4 lanes per batch, prefetched) ------
__global__ __launch_bounds__(32)
void smooth_kernel(const float* __restrict__ mu_f, const float* __restrict__ mu_p,
                   const float* __restrict__ Jg, float* __restrict__ mus)
{
    int tid = threadIdx.x;
    int g = blockIdx.x*8 + (tid>>2);
    int i = tid & 3;
    size_t base = (size_t)g*TT_;
    float v = mu_f[(base+TT_-1)*4 + i];
    mus[(base+TT_-1)*4 + i] = v;
    unsigned gb = tid & ~3u;
    float4 Jr = *(const float4*)&Jg[(base+TT_-2)*16 + i*4];
    float mf = mu_f[(base+TT_-2)*4 + i];
    float mp = mu_p[(base+TT_-1)*4 + i];
    for (int t=TT_-2; t>=0; t--){
        float4 Jn; float mfn=0.f, mpn=0.f;
        if (t>0){
            Jn  = *(const float4*)&Jg[(base+t-1)*16 + i*4];
            mfn = mu_f[(base+t-1)*4 + i];
            mpn = mu_p[(base+t)*4 + i];
        } else { Jn = Jr; }
        float mi = v - mp;
        float m0=__shfl_sync(0xffffffffu, mi, gb+0);
        float m1=__shfl_sync(0xffffffffu, mi, gb+1);
        float m2=__shfl_sync(0xffffffffu, mi, gb+2);
        float m3=__shfl_sync(0xffffffffu, mi, gb+3);
        v = mf + Jr.x*m0 + Jr.y*m1 + Jr.z*m2 + Jr.w*m3;
        mus[(base+t)*4+i]=v;
        Jr=Jn; mf=mfn; mp=mpn;
    }
}

// ---------------- a_hat = C_mix mu_smooth -------------------------------------------
__global__ void ahat_kernel(const float* __restrict__ alpha, const float* __restrict__ mus,
                            const float* __restrict__ Cg, float* __restrict__ ahat)
{
    int idx = blockIdx.x*blockDim.x + threadIdx.x;
    if (idx >= NROWS) return;
    float a0=alpha[(size_t)idx*3+0], a1=alpha[(size_t)idx*3+1], a2=alpha[(size_t)idx*3+2];
    float4 mu = *(const float4*)&mus[(size_t)idx*4];
    float mv[4]={mu.x,mu.y,mu.z,mu.w};
#pragma unroll
    for (int r=0;r<8;r++){
        float v=0.f;
#pragma unroll
        for (int j=0;j<4;j++){
            float cm = a0*__ldg(&Cg[r*4+j]) + a1*__ldg(&Cg[32+r*4+j]) + a2*__ldg(&Cg[64+r*4+j]);
            v += cm*mv[j];
        }
        ahat[(size_t)idx*8+r]=v;
    }
}

// ---------------- decoder layer 1: d1 = tanh(ahat @ W^T + b) (K=8) ------------------
__global__ __launch_bounds__(256)
void dec1_kernel(const float* __restrict__ ahat, const float* __restrict__ W,
                 const float* __restrict__ bvec, float* __restrict__ out)
{
    __shared__ float sa[16][8];
    int tid = threadIdx.x;
    int r0 = blockIdx.x*16;
    if (tid<128) sa[tid>>3][tid&7] = ahat[(size_t)r0*8 + tid];
    int n = tid & 127;
    float w[8];
#pragma unroll
    for (int j=0;j<8;j++) w[j]=W[n*8+j];
    float bb=bvec[n];
    __syncthreads();
    int half = tid>>7;
#pragma unroll
    for (int q=0;q<8;q++){
        int rl = half*8+q;
        float s=bb;
#pragma unroll
        for (int j=0;j<8;j++) s += sa[rl][j]*w[j];
        out[(size_t)(r0+rl)*128 + n] = ftanh(s);
    }
}

// ---------------- launcher ----------------------------------------------------------
extern "C" void kernel_launch(void* const* d_in, const int* in_sizes, int n_in,
                              void* d_out, int out_size)
{
    const float* x       = (const float*)d_in[0];
    const float* m       = (const float*)d_in[1];
    const float* u_ext   = (const float*)d_in[2];
    const float* eps     = (const float*)d_in[3];
    const float* enc_W1  = (const float*)d_in[4];
    const float* enc_b1  = (const float*)d_in[5];
    const float* enc_W2  = (const float*)d_in[6];
    const float* enc_b2  = (const float*)d_in[7];
    const float* W_mean  = (const float*)d_in[8];
    const float* b_mean  = (const float*)d_in[9];
    const float* Amat    = (const float*)d_in[10];
    const float* Bmat    = (const float*)d_in[11];
    const float* Cmat    = (const float*)d_in[12];
    const float* a_init  = (const float*)d_in[13];
    const float* lstm_Wih= (const float*)d_in[14];
    const float* lstm_Whh= (const float*)d_in[15];
    const float* lstm_bih= (const float*)d_in[16];
    const float* lstm_bhh= (const float*)d_in[17];
    const float* alpha_W = (const float*)d_in[18];
    const float* alpha_b = (const float*)d_in[19];
    const float* dec_W1  = (const float*)d_in[20];
    const float* dec_b1  = (const float*)d_in[21];
    const float* dec_W2  = (const float*)d_in[22];
    const float* dec_b2  = (const float*)d_in[23];
    const float* gen_W   = (const float*)d_in[24];
    const float* gen_b   = (const float*)d_in[25];

    float *p_buf1,*p_buf2,*p_a,*p_alpha,*p_mup,*p_muf,*p_J,*p_mus,*p_ahat;
    cudaGetSymbolAddress((void**)&p_buf1,  g_buf1);
    cudaGetSymbolAddress((void**)&p_buf2,  g_buf2);
    cudaGetSymbolAddress((void**)&p_a,     g_a);
    cudaGetSymbolAddress((void**)&p_alpha, g_alpha);
    cudaGetSymbolAddress((void**)&p_mup,   g_mup);
    cudaGetSymbolAddress((void**)&p_muf,   g_muf);
    cudaGetSymbolAddress((void**)&p_J,     g_J);
    cudaGetSymbolAddress((void**)&p_mus,   g_mus);
    cudaGetSymbolAddress((void**)&p_ahat,  g_ahat);

    // encoder
    sgemm128<1,true ><<<NROWS/128,256>>>(x, m, enc_W1, enc_b1, p_buf1, 256);
    sgemm128<1,false><<<NROWS/128,256>>>(p_buf1, nullptr, enc_W2, enc_b2, p_buf2, 128);
    enc3_kernel<<<NROWS/32,256>>>(p_buf2, W_mean, b_mean, eps, p_a);
    // LSTM -> alpha
    lstm_kernel<<<BSZ,256>>>(p_a, a_init, lstm_Wih, lstm_Whh, lstm_bih, lstm_bhh,
                             alpha_W, alpha_b, p_alpha);
    // Kalman forward (+ fused smoother gains J, information-form covariance)
    kf_forward<<<BSZ/2,64>>>(p_alpha, p_a, a_init, u_ext, Amat, Bmat, Cmat,
                             p_mup, p_muf, p_J);
    // backward mu recursion
    smooth_kernel<<<32,32>>>(p_muf, p_mup, p_J, p_mus);
    ahat_kernel<<<NROWS/256,256>>>(p_alpha, p_mus, Cmat, p_ahat);
    // decoder
    dec1_kernel<<<NROWS/16,256>>>(p_ahat, dec_W1, dec_b1, p_buf1);
    sgemm128<1,false><<<NROWS/128,256>>>(p_buf1, nullptr, dec_W2, dec_b2, p_buf2, 128);
    sgemm128<2,false><<<NROWS/128,256>>>(p_buf2, nullptr, gen_W, gen_b, (float*)d_out, 128);
    (void)in_sizes; (void)n_in; (void)out_size;
}

// round 5
// speedup vs baseline: 1.2705x; 1.2705x over previous
#include <cuda_runtime.h>
#include <math.h>
#include <stdint.h>

#define BSZ 256
#define TT_ 512
#define ADIM 8
#define ZDIM 4
#define KMIX 3
#define HL 50
#define HID 128
#define NROWS (BSZ*TT_)

// ---------------- scratch (static __device__; cudaMalloc forbidden) ----------------
__device__ float g_buf1[NROWS*HID];
__device__ float g_buf2[NROWS*HID];
__device__ float g_a[NROWS*ADIM];
__device__ float g_alpha[NROWS*KMIX];
__device__ float g_mup[NROWS*ZDIM];
__device__ float g_muf[NROWS*ZDIM];
__device__ float g_J[NROWS*ZDIM*ZDIM];
__device__ float g_mus[NROWS*ZDIM];
__device__ float g_ahat[NROWS*ADIM];

// ---------------- fast activations ----------------
__device__ __forceinline__ float fsig(float x){
    return __fdividef(1.f, 1.f + __expf(-x));
}
__device__ __forceinline__ float ftanh(float x){
    float xc = fminf(fmaxf(x, -15.f), 15.f);
    float t = __expf(2.f*xc);
    return __fdividef(t-1.f, t+1.f);
}

template<int ACT>
__device__ __forceinline__ float actf(float v){
    if (ACT == 1) return ftanh(v);
    if (ACT == 2) return fsig(v);
    return v;
}

// ---------------- tf32 helpers ------------------------------------------------------
__device__ __forceinline__ uint32_t tf32_of(float x){
    uint32_t r;
    asm("cvt.rna.tf32.f32 %0, %1;" : "=r"(r) : "f"(x));
    return r;
}
__device__ __forceinline__ void mma_tf32(float* d, const uint32_t* a, const uint32_t* b){
    asm volatile("mma.sync.aligned.m16n8k8.row.col.f32.tf32.tf32.f32 "
        "{%0,%1,%2,%3},{%4,%5,%6,%7},{%8,%9},{%0,%1,%2,%3};"
        : "+f"(d[0]),"+f"(d[1]),"+f"(d[2]),"+f"(d[3])
        : "r"(a[0]),"r"(a[1]),"r"(a[2]),"r"(a[3]),"r"(b[0]),"r"(b[1]));
}

// ---------------- tf32 tensor-core GEMM: C[M,128] = act(A[M,K] @ W[128,K]^T + b) ----
// Block tile 128x128, 8 warps (4 along m, 2 along n), warp tile 32x64.
// mma m16n8k8: A row-major frags from sA[m][k] (stride 36), B col-major frags from
// sW[n][k] (stride 36). Both patterns conflict-free (bank = 4*g+q, all distinct).
template<int ACT, bool CONCAT>
__global__ __launch_bounds__(256)
void tgemm128(const float* __restrict__ A0, const float* __restrict__ A1,
              const float* __restrict__ W, const float* __restrict__ bias,
              float* __restrict__ C, int K)
{
    __shared__ __align__(16) float sA[128][36];
    __shared__ __align__(16) float sW[128][36];
    const int tid = threadIdx.x;
    const int wid = tid>>5, ln = tid&31;
    const int g = ln>>2, q = ln&3;
    const int wm = (wid&3)*32;
    const int wn = (wid>>2)*64;
    const int row0 = blockIdx.x*128;

    float d[2][8][4];
#pragma unroll
    for (int mt=0;mt<2;mt++)
#pragma unroll
        for (int nt=0;nt<8;nt++)
#pragma unroll
            for (int i=0;i<4;i++) d[mt][nt][i]=0.f;

    for (int k0=0;k0<K;k0+=32){
        __syncthreads();
        // A tile: 128 rows x 32 k (1024 float4, 4 per thread)
#pragma unroll
        for (int it=0;it<4;it++){
            int idx = tid + it*256;
            int r = idx>>3, c4 = (idx&7)*4;
            const float* src;
            if (CONCAT){
                int gk = k0 + c4;
                src = (gk<128)? (A0+(size_t)(row0+r)*128+gk)
                              : (A1+(size_t)(row0+r)*128+(gk-128));
            } else {
                src = A0+(size_t)(row0+r)*K + k0 + c4;
            }
            float4 v = *(const float4*)src;
            float4 o;
            o.x=__uint_as_float(tf32_of(v.x)); o.y=__uint_as_float(tf32_of(v.y));
            o.z=__uint_as_float(tf32_of(v.z)); o.w=__uint_as_float(tf32_of(v.w));
            *(float4*)&sA[r][c4] = o;
        }
        // W tile: 128 n x 32 k
#pragma unroll
        for (int it=0;it<4;it++){
            int idx = tid + it*256;
            int n = idx>>3, c4 = (idx&7)*4;
            float4 v = *(const float4*)(W+(size_t)n*K + k0 + c4);
            float4 o;
            o.x=__uint_as_float(tf32_of(v.x)); o.y=__uint_as_float(tf32_of(v.y));
            o.z=__uint_as_float(tf32_of(v.z)); o.w=__uint_as_float(tf32_of(v.w));
            *(float4*)&sW[n][c4] = o;
        }
        __syncthreads();
#pragma unroll
        for (int kk=0;kk<32;kk+=8){
            uint32_t af[2][4];
#pragma unroll
            for (int mt=0;mt<2;mt++){
                int mr = wm + mt*16;
                af[mt][0]=__float_as_uint(sA[mr+g  ][kk+q  ]);
                af[mt][1]=__float_as_uint(sA[mr+g+8][kk+q  ]);
                af[mt][2]=__float_as_uint(sA[mr+g  ][kk+q+4]);
                af[mt][3]=__float_as_uint(sA[mr+g+8][kk+q+4]);
            }
            uint32_t bf[8][2];
#pragma unroll
            for (int nt=0;nt<8;nt++){
                int nc = wn + nt*8 + g;
                bf[nt][0]=__float_as_uint(sW[nc][kk+q  ]);
                bf[nt][1]=__float_as_uint(sW[nc][kk+q+4]);
            }
#pragma unroll
            for (int mt=0;mt<2;mt++)
#pragma unroll
                for (int nt=0;nt<8;nt++)
                    mma_tf32(d[mt][nt], af[mt], bf[nt]);
        }
    }
    // epilogue: bias + activation, float2 stores
#pragma unroll
    for (int mt=0;mt<2;mt++){
        int r_top = row0 + wm + mt*16 + g;
#pragma unroll
        for (int nt=0;nt<8;nt++){
            int col = wn + nt*8 + 2*q;
            float b0v = bias[col], b1v = bias[col+1];
            float2 o0, o1;
            o0.x = actf<ACT>(d[mt][nt][0]+b0v);
            o0.y = actf<ACT>(d[mt][nt][1]+b1v);
            o1.x = actf<ACT>(d[mt][nt][2]+b0v);
            o1.y = actf<ACT>(d[mt][nt][3]+b1v);
            *(float2*)&C[(size_t)r_top*128 + col]     = o0;
            *(float2*)&C[(size_t)(r_top+8)*128 + col] = o1;
        }
    }
}

// ---------------- encoder layer 3: a = Y2 @ Wm^T + bm + eps  (N=8, K=128) ----------
__global__ __launch_bounds__(256)
void enc3_kernel(const float* __restrict__ Y2, const float* __restrict__ Wm,
                 const float* __restrict__ bm, const float* __restrict__ eps,
                 float* __restrict__ aout)
{
    __shared__ __align__(16) float sW[8][128];
    for (int i=threadIdx.x;i<1024;i+=256) sW[i>>7][i&127]=Wm[i];
    __syncthreads();
    int r = blockIdx.x*32 + (threadIdx.x>>3);
    int n = threadIdx.x&7;
    const float4* y = (const float4*)(Y2 + (size_t)r*128);
    const float4* w = (const float4*)&sW[n][0];
    float s=0.f;
#pragma unroll
    for (int k=0;k<32;k++){
        float4 yv=y[k], wv=w[k];
        s += yv.x*wv.x+yv.y*wv.y+yv.z*wv.z+yv.w*wv.w;
    }
    aout[(size_t)r*8+n] = s + bm[n] + eps[(size_t)r*8+n];
}

// ---------------- LSTM + alpha (R3 version): 2 syncs/step, pipelined alpha ---------
__global__ __launch_bounds__(256)
void lstm_kernel(const float* __restrict__ a, const float* __restrict__ a_init,
                 const float* __restrict__ Wih, const float* __restrict__ Whh,
                 const float* __restrict__ bih, const float* __restrict__ bhh,
                 const float* __restrict__ aW, const float* __restrict__ ab,
                 float* __restrict__ alpha)
{
    __shared__ __align__(16) float4 shv[13];      // h, padded to 52
    __shared__ __align__(16) float4 sxv[2][2];    // x_t, double buffered (8)
    __shared__ float spre[200];
    __shared__ __align__(16) float4 saWv[3][13];
    __shared__ float sab_s[3];
    __shared__ float slog[3];
    int tid=threadIdx.x; int b=blockIdx.x;

    float wih[8], whh[52], bsum=0.f, c=0.f;
    if (tid<200){
#pragma unroll
        for (int j=0;j<8;j++) wih[j]=Wih[tid*8+j];
#pragma unroll
        for (int j=0;j<50;j++) whh[j]=Whh[tid*50+j];
        whh[50]=0.f; whh[51]=0.f;
        bsum = bih[tid]+bhh[tid];
    }
    for (int i=tid;i<3*52;i+=256){
        int row=i/52, col=i%52;
        ((float*)saWv)[i] = (col<50)? aW[row*50+col] : 0.f;
    }
    if (tid<3) sab_s[tid]=ab[tid];
    for (int i=tid;i<52;i+=256) ((float*)shv)[i]=0.f;
    if (tid<8) ((float*)sxv)[tid]=a_init[tid];    // sxv[0] = a_init
    __syncthreads();

    for (int t=0;t<TT_;t++){
        int pb = t&1;
        // ---- P1 ----
        if (tid<200){
            const float4* xv = sxv[pb];
            float4 x0=xv[0], x1=xv[1];
            float a0 = bsum + wih[0]*x0.x + wih[4]*x1.x;
            float a1 = wih[1]*x0.y + wih[5]*x1.y;
            float a2 = wih[2]*x0.z + wih[6]*x1.z;
            float a3 = wih[3]*x0.w + wih[7]*x1.w;
#pragma unroll
            for (int q=0;q<13;q++){
                float4 hv=shv[q];
                a0 += whh[4*q+0]*hv.x;
                a1 += whh[4*q+1]*hv.y;
                a2 += whh[4*q+2]*hv.z;
                a3 += whh[4*q+3]*hv.w;
            }
            spre[tid]=(a0+a1)+(a2+a3);
        } else if (tid>=224 && tid<227){
            if (t>0){
                int k=tid-224;
                float a0=0,a1=0,a2=0,a3=0;
#pragma unroll
                for (int q=0;q<13;q++){
                    float4 wv=saWv[k][q], hv=shv[q];
                    a0+=wv.x*hv.x; a1+=wv.y*hv.y; a2+=wv.z*hv.z; a3+=wv.w*hv.w;
                }
                slog[k]=(a0+a1)+(a2+a3)+sab_s[k];
            }
        } else if (tid>=232 && tid<240){
            if (t<TT_-1)
                ((float*)sxv[pb^1])[tid-232] = a[((size_t)b*TT_+t)*8 + (tid-232)];
        }
        __syncthreads();
        // ---- P2 ----
        if (tid<50){
            float pi=spre[tid], pf=spre[50+tid], pg=spre[100+tid], po=spre[150+tid];
            float ig=fsig(pi);
            float fg=fsig(pf);
            float gg=ftanh(pg);
            float og=fsig(po);
            c = fg*c + ig*gg;
            ((float*)shv)[tid] = og*ftanh(c);
        } else if (tid>=224 && tid<227 && t>0){
            int k=tid-224;
            float l0=slog[0],l1=slog[1],l2=slog[2];
            float mx=fmaxf(l0,fmaxf(l1,l2));
            float e0=__expf(l0-mx),e1=__expf(l1-mx),e2=__expf(l2-mx);
            float inv=__fdividef(1.f, e0+e1+e2);
            float mine=(k==0)?e0:((k==1)?e1:e2);
            alpha[((size_t)b*TT_+t-1)*3+k]=mine*inv;
        }
        __syncthreads();
    }
    // final alpha (t = T-1) from h_{T-1}
    if (tid>=224 && tid<227){
        int k=tid-224;
        float lg[3];
#pragma unroll
        for (int kk=0;kk<3;kk++){
            float a0=0,a1=0,a2=0,a3=0;
#pragma unroll
            for (int q=0;q<13;q++){
                float4 wv=saWv[kk][q], hv=shv[q];
                a0+=wv.x*hv.x; a1+=wv.y*hv.y; a2+=wv.z*hv.z; a3+=wv.w*hv.w;
            }
            lg[kk]=(a0+a1)+(a2+a3)+sab_s[kk];
        }
        float mx=fmaxf(lg[0],fmaxf(lg[1],lg[2]));
        float e0=__expf(lg[0]-mx),e1=__expf(lg[1]-mx),e2=__expf(lg[2]-mx);
        float inv=__fdividef(1.f, e0+e1+e2);
        float mine=(k==0)?e0:((k==1)?e1:e2);
        alpha[((size_t)b*TT_+TT_-1)*3+k]=mine*inv;
    }
}

// ---------------- 4x4 determinant + adjugate helpers --------------------------------
__device__ __forceinline__ float det4s(const float* m){
    float m00=m[0],m01=m[1],m02=m[2],m03=m[3];
    float m10=m[4],m11=m[5],m12=m[6],m13=m[7];
    float m20=m[8],m21=m[9],m22=m[10],m23=m[11];
    float m30=m[12],m31=m[13],m32=m[14],m33=m[15];
    return m00*(m11*(m22*m33-m23*m32)-m12*(m21*m33-m23*m31)+m13*(m21*m32-m22*m31))
         - m01*(m10*(m22*m33-m23*m32)-m12*(m20*m33-m23*m30)+m13*(m20*m32-m22*m30))
         + m02*(m10*(m21*m33-m23*m31)-m11*(m20*m33-m23*m30)+m13*(m20*m31-m21*m30))
         - m03*(m10*(m21*m32-m22*m31)-m11*(m20*m32-m22*m30)+m12*(m20*m31-m21*m30));
}

__device__ __forceinline__ float adj_entry(const float* m, int l){
    int r=l>>2, c=l&3;
    int rr[3], cc[3];
    int p=0;
#pragma unroll
    for (int k=0;k<4;k++) if (k!=c) rr[p++]=k;
    p=0;
#pragma unroll
    for (int k=0;k<4;k++) if (k!=r) cc[p++]=k;
    float a00=m[rr[0]*4+cc[0]], a01=m[rr[0]*4+cc[1]], a02=m[rr[0]*4+cc[2]];
    float a10=m[rr[1]*4+cc[0]], a11=m[rr[1]*4+cc[1]], a12=m[rr[1]*4+cc[2]];
    float a20=m[rr[2]*4+cc[0]], a21=m[rr[2]*4+cc[1]], a22=m[rr[2]*4+cc[2]];
    float d = a00*(a11*a22-a12*a21) - a01*(a10*a22-a12*a20) + a02*(a10*a21-a11*a20);
    return ((r+c)&1)? -d : d;
}

// ---------------- Kalman forward + smoother gains (information form, 9 phases) -----
#define KO_AM   0
#define KO_BM   16
#define KO_CM   52
#define KO_SIG  84
#define KO_SIGP 100
#define KO_PADJ 116
#define KO_CTC  132
#define KO_N    148
#define KO_NADJ 164
#define KO_T2   180
#define KO_JT   196
#define KO_KG   212
#define KO_MU   244
#define KO_MUP  248
#define KO_RES  252
#define KO_AT   260
#define KO_UT   268
#define KO_AL   277
#define KO_SC   280
#define KWSZ    288

__global__ __launch_bounds__(64)
void kf_forward(const float* __restrict__ alpha, const float* __restrict__ a,
                const float* __restrict__ a_init, const float* __restrict__ u_ext,
                const float* __restrict__ Ag, const float* __restrict__ Bg,
                const float* __restrict__ Cg,
                float* __restrict__ mu_p_g, float* __restrict__ mu_f_g,
                float* __restrict__ Jg)
{
    __shared__ float sA[48], sB[108], sC[96];
    __shared__ float wsm[2][KWSZ];
    const float qn=0.08f, ir=1.f/0.03f;
    int w = threadIdx.x>>5, ln = threadIdx.x&31;
    int b = blockIdx.x*2 + w;
    for (int i=threadIdx.x;i<48;i+=64) sA[i]=Ag[i];
    for (int i=threadIdx.x;i<108;i+=64) sB[i]=Bg[i];
    for (int i=threadIdx.x;i<96;i+=64) sC[i]=Cg[i];
    __syncthreads();
    float* s = wsm[w];

    float r_al=0.f, r_a=0.f, r_u=0.f, r_ap=0.f;
    if (ln<3)            r_al = alpha[(size_t)b*TT_*3 + ln];
    if (ln>=4 && ln<12){ r_a  = a[(size_t)b*TT_*8 + (ln-4)]; r_ap = a_init[ln-4]; }
    if (ln==12)          r_u  = u_ext[(size_t)b*TT_];

    for (int t=0;t<TT_;t++){
        size_t bt = (size_t)b*TT_ + t;
        if (ln<3) s[KO_AL+ln]=r_al;
        if (ln>=4 && ln<12){ s[KO_AT+ln-4]=r_a; s[KO_UT+ln-4]=r_ap; r_ap=r_a; }
        if (ln==12) s[KO_UT+8]=r_u;
        __syncwarp();
        if (t+1<TT_){
            if (ln<3)            r_al = alpha[(bt+1)*3+ln];
            if (ln>=4 && ln<12)  r_a  = a[(bt+1)*8 + (ln-4)];
            if (ln==12)          r_u  = u_ext[bt+1];
        }
        float al0=s[KO_AL], al1=s[KO_AL+1], al2=s[KO_AL+2];
        for (int f=ln; f<84; f+=32){
            if (f<16)      s[KO_AM+f] = al0*sA[f] + al1*sA[16+f] + al2*sA[32+f];
            else if (f<52){int j2=f-16; s[KO_BM+j2]=al0*sB[j2]+al1*sB[36+j2]+al2*sB[72+j2];}
            else          {int j2=f-52; s[KO_CM+j2]=al0*sC[j2]+al1*sC[32+j2]+al2*sC[64+j2];}
        }
        __syncwarp();
        if (t==0){
            if (ln<4) s[KO_MUP+ln]=0.f;
            if (ln>=16){int l=ln-16; s[KO_SIGP+l]=((l>>2)==(l&3))?20.f:0.f;}
        } else {
            if (ln<4){
                float v=0.f;
#pragma unroll
                for (int j=0;j<4;j++) v += s[KO_AM+ln*4+j]*s[KO_MU+j];
#pragma unroll
                for (int j=0;j<9;j++) v += s[KO_BM+ln*9+j]*s[KO_UT+j];
                s[KO_MUP+ln]=v;
            }
            if (ln>=16){
                int l=ln-16, i=l>>2, j=l&3;
                float v=(i==j)?qn:0.f;
#pragma unroll
                for (int k=0;k<4;k++){
                    float inner=0.f;
#pragma unroll
                    for (int q=0;q<4;q++) inner += s[KO_SIG+k*4+q]*s[KO_AM+j*4+q];
                    v += s[KO_AM+i*4+k]*inner;
                }
                s[KO_SIGP+l]=v;
            }
        }
        if (ln>=4 && ln<14){
            const int pi_[10]={0,0,0,0,1,1,1,2,2,3};
            const int pj_[10]={0,1,2,3,1,2,3,2,3,3};
            int l=ln-4, i=pi_[l], j=pj_[l];
            float v=0.f;
#pragma unroll
            for (int cc=0;cc<8;cc++) v += s[KO_CM+cc*4+i]*s[KO_CM+cc*4+j];
            v*=ir;
            s[KO_CTC+i*4+j]=v; s[KO_CTC+j*4+i]=v;
        }
        __syncwarp();
        if (ln<16) s[KO_PADJ+ln]=adj_entry(s+KO_SIGP, ln);
        else if (t>0){
            int l=ln-16, i=l>>2, j=l&3; float v=0.f;
#pragma unroll
            for (int k=0;k<4;k++) v += s[KO_SIG+i*4+k]*s[KO_AM+j*4+k];
            s[KO_T2+l]=v;
        }
        __syncwarp();
        if (ln==0){
            float dp = s[KO_SIGP+0]*s[KO_PADJ+0] + s[KO_SIGP+1]*s[KO_PADJ+4]
                     + s[KO_SIGP+2]*s[KO_PADJ+8] + s[KO_SIGP+3]*s[KO_PADJ+12];
            s[KO_SC+0]=dp;
            s[KO_SC+1]=__fdividef(1.f,dp);
        }
        if (ln>=8 && ln<16){
            int cc=ln-8; float v=s[KO_AT+cc];
#pragma unroll
            for (int k=0;k<4;k++) v -= s[KO_CM+cc*4+k]*s[KO_MUP+k];
            s[KO_RES+cc]=v;
        }
        if (t>0 && ln>=16){
            int l=ln-16, i=l>>2, j=l&3; float v=0.f;
#pragma unroll
            for (int k=0;k<4;k++) v += s[KO_T2+i*4+k]*s[KO_PADJ+k*4+j];
            s[KO_JT+l]=v;
        }
        __syncwarp();
        if (ln<16) s[KO_N+ln] = s[KO_PADJ+ln] + s[KO_SC+0]*s[KO_CTC+ln];
        else if (t>0){
            int l=ln-16;
            Jg[(bt-1)*16 + l] = s[KO_JT+l]*s[KO_SC+1];
        }
        __syncwarp();
        if (ln<16) s[KO_NADJ+ln]=adj_entry(s+KO_N, ln);
        if (ln==16){
            float dn = det4s(s+KO_N);
            float sc = __fdividef(s[KO_SC+0], dn);
            s[KO_SC+2]=sc;
            s[KO_SC+3]=sc*ir;
        }
        __syncwarp();
        {
            int i=ln>>3, cc=ln&7; float v=0.f;
#pragma unroll
            for (int k=0;k<4;k++) v += s[KO_NADJ+i*4+k]*s[KO_CM+cc*4+k];
            s[KO_KG+i*8+cc]=v;
        }
        __syncwarp();
        if (ln>=16){
            int l=ln-16;
            s[KO_SIG+l]=s[KO_NADJ+l]*s[KO_SC+2];
        }
        if (ln<4){
            float acc=0.f;
#pragma unroll
            for (int cc=0;cc<8;cc++) acc += s[KO_KG+ln*8+cc]*s[KO_RES+cc];
            float v = s[KO_MUP+ln] + acc*s[KO_SC+3];
            s[KO_MU+ln]=v;
            mu_f_g[bt*4+ln]=v;
        }
        if (ln>=4 && ln<8) mu_p_g[bt*4+ln-4]=s[KO_MUP+ln-4];
        __syncwarp();
    }
}

// ---------------- backward mu_smooth recursion (4 lanes per batch, prefetched) ------
__global__ __launch_bounds__(32)
void smooth_kernel(const float* __restrict__ mu_f, const float* __restrict__ mu_p,
                   const float* __restrict__ Jg, float* __restrict__ mus)
{
    int tid = threadIdx.x;
    int g = blockIdx.x*8 + (tid>>2);
    int i = tid & 3;
    size_t base = (size_t)g*TT_;
    float v = mu_f[(base+TT_-1)*4 + i];
    mus[(base+TT_-1)*4 + i] = v;
    unsigned gb = tid & ~3u;
    float4 Jr = *(const float4*)&Jg[(base+TT_-2)*16 + i*4];
    float mf = mu_f[(base+TT_-2)*4 + i];
    float mp = mu_p[(base+TT_-1)*4 + i];
    for (int t=TT_-2; t>=0; t--){
        float4 Jn; float mfn=0.f, mpn=0.f;
        if (t>0){
            Jn  = *(const float4*)&Jg[(base+t-1)*16 + i*4];
            mfn = mu_f[(base+t-1)*4 + i];
            mpn = mu_p[(base+t)*4 + i];
        } else { Jn = Jr; }
        float mi = v - mp;
        float m0=__shfl_sync(0xffffffffu, mi, gb+0);
        float m1=__shfl_sync(0xffffffffu, mi, gb+1);
        float m2=__shfl_sync(0xffffffffu, mi, gb+2);
        float m3=__shfl_sync(0xffffffffu, mi, gb+3);
        v = mf + Jr.x*m0 + Jr.y*m1 + Jr.z*m2 + Jr.w*m3;
        mus[(base+t)*4+i]=v;
        Jr=Jn; mf=mfn; mp=mpn;
    }
}

// ---------------- a_hat = C_mix mu_smooth -------------------------------------------
__global__ void ahat_kernel(const float* __restrict__ alpha, const float* __restrict__ mus,
                            const float* __restrict__ Cg, float* __restrict__ ahat)
{
    int idx = blockIdx.x*blockDim.x + threadIdx.x;
    if (idx >= NROWS) return;
    float a0=alpha[(size_t)idx*3+0], a1=alpha[(size_t)idx*3+1], a2=alpha[(size_t)idx*3+2];
    float4 mu = *(const float4*)&mus[(size_t)idx*4];
    float mv[4]={mu.x,mu.y,mu.z,mu.w};
#pragma unroll
    for (int r=0;r<8;r++){
        float v=0.f;
#pragma unroll
        for (int j=0;j<4;j++){
            float cm = a0*__ldg(&Cg[r*4+j]) + a1*__ldg(&Cg[32+r*4+j]) + a2*__ldg(&Cg[64+r*4+j]);
            v += cm*mv[j];
        }
        ahat[(size_t)idx*8+r]=v;
    }
}

// ---------------- decoder layer 1: d1 = tanh(ahat @ W^T + b) (K=8) ------------------
__global__ __launch_bounds__(256)
void dec1_kernel(const float* __restrict__ ahat, const float* __restrict__ W,
                 const float* __restrict__ bvec, float* __restrict__ out)
{
    __shared__ float sa[16][8];
    int tid = threadIdx.x;
    int r0 = blockIdx.x*16;
    if (tid<128) sa[tid>>3][tid&7] = ahat[(size_t)r0*8 + tid];
    int n = tid & 127;
    float w[8];
#pragma unroll
    for (int j=0;j<8;j++) w[j]=W[n*8+j];
    float bb=bvec[n];
    __syncthreads();
    int half = tid>>7;
#pragma unroll
    for (int q=0;q<8;q++){
        int rl = half*8+q;
        float s=bb;
#pragma unroll
        for (int j=0;j<8;j++) s += sa[rl][j]*w[j];
        out[(size_t)(r0+rl)*128 + n] = ftanh(s);
    }
}

// ---------------- launcher ----------------------------------------------------------
extern "C" void kernel_launch(void* const* d_in, const int* in_sizes, int n_in,
                              void* d_out, int out_size)
{
    const float* x       = (const float*)d_in[0];
    const float* m       = (const float*)d_in[1];
    const float* u_ext   = (const float*)d_in[2];
    const float* eps     = (const float*)d_in[3];
    const float* enc_W1  = (const float*)d_in[4];
    const float* enc_b1  = (const float*)d_in[5];
    const float* enc_W2  = (const float*)d_in[6];
    const float* enc_b2  = (const float*)d_in[7];
    const float* W_mean  = (const float*)d_in[8];
    const float* b_mean  = (const float*)d_in[9];
    const float* Amat    = (const float*)d_in[10];
    const float* Bmat    = (const float*)d_in[11];
    const float* Cmat    = (const float*)d_in[12];
    const float* a_init  = (const float*)d_in[13];
    const float* lstm_Wih= (const float*)d_in[14];
    const float* lstm_Whh= (const float*)d_in[15];
    const float* lstm_bih= (const float*)d_in[16];
    const float* lstm_bhh= (const float*)d_in[17];
    const float* alpha_W = (const float*)d_in[18];
    const float* alpha_b = (const float*)d_in[19];
    const float* dec_W1  = (const float*)d_in[20];
    const float* dec_b1  = (const float*)d_in[21];
    const float* dec_W2  = (const float*)d_in[22];
    const float* dec_b2  = (const float*)d_in[23];
    const float* gen_W   = (const float*)d_in[24];
    const float* gen_b   = (const float*)d_in[25];

    float *p_buf1,*p_buf2,*p_a,*p_alpha,*p_mup,*p_muf,*p_J,*p_mus,*p_ahat;
    cudaGetSymbolAddress((void**)&p_buf1,  g_buf1);
    cudaGetSymbolAddress((void**)&p_buf2,  g_buf2);
    cudaGetSymbolAddress((void**)&p_a,     g_a);
    cudaGetSymbolAddress((void**)&p_alpha, g_alpha);
    cudaGetSymbolAddress((void**)&p_mup,   g_mup);
    cudaGetSymbolAddress((void**)&p_muf,   g_muf);
    cudaGetSymbolAddress((void**)&p_J,     g_J);
    cudaGetSymbolAddress((void**)&p_mus,   g_mus);
    cudaGetSymbolAddress((void**)&p_ahat,  g_ahat);

    // encoder (tf32 tensor cores)
    tgemm128<1,true ><<<NROWS/128,256>>>(x, m, enc_W1, enc_b1, p_buf1, 256);
    tgemm128<1,false><<<NROWS/128,256>>>(p_buf1, nullptr, enc_W2, enc_b2, p_buf2, 128);
    enc3_kernel<<<NROWS/32,256>>>(p_buf2, W_mean, b_mean, eps, p_a);
    // LSTM -> alpha
    lstm_kernel<<<BSZ,256>>>(p_a, a_init, lstm_Wih, lstm_Whh, lstm_bih, lstm_bhh,
                             alpha_W, alpha_b, p_alpha);
    // Kalman forward (+ fused smoother gains J)
    kf_forward<<<BSZ/2,64>>>(p_alpha, p_a, a_init, u_ext, Amat, Bmat, Cmat,
                             p_mup, p_muf, p_J);
    // backward mu recursion
    smooth_kernel<<<32,32>>>(p_muf, p_mup, p_J, p_mus);
    ahat_kernel<<<NROWS/256,256>>>(p_alpha, p_mus, Cmat, p_ahat);
    // decoder (tf32 tensor cores)
    dec1_kernel<<<NROWS/16,256>>>(p_ahat, dec_W1, dec_b1, p_buf1);
    tgemm128<1,false><<<NROWS/128,256>>>(p_buf1, nullptr, dec_W2, dec_b2, p_buf2, 128);
    tgemm128<2,false><<<NROWS/128,256>>>(p_buf2, nullptr, gen_W, gen_b, (float*)d_out, 128);
    (void)in_sizes; (void)n_in; (void)out_size;
}